// round 6
// baseline (speedup 1.0000x reference)
#include <cuda_runtime.h>

typedef unsigned long long ull;

#define BATCH   128
#define TSTEPS  512
#define NDIM    512
#define NIN     6

#define BG_COUNT 8       // batch groups (16 rows each)
#define NG_COUNT 16      // n groups (32 cols each)
#define TILE_B   16
#define TILE_N   32
#define NTHREADS 128
#define K4       128     // 512 / 4 (float4 chunks along k)

#define SMEM_W_BYTES (K4 * TILE_N * 16)   // 65536
#define SMEM_H_BYTES (TILE_B * K4 * 16)   // 32768
#define SMEM_BYTES   (SMEM_W_BYTES + SMEM_H_BYTES + 4096)

// Persistent scratch (allowed: __device__ globals). Ping-pong h buffers + flags.
__device__ float4 g_hbuf[2][BATCH * NDIM / 4];
__device__ ull    g_flags[BG_COUNT * NG_COUNT];   // zero-initialized, monotonic across runs

__device__ __forceinline__ void ffma2(ull &acc, ull a, ull b) {
    asm("fma.rn.f32x2 %0, %1, %2, %0;" : "+l"(acc) : "l"(a), "l"(b));
}
__device__ __forceinline__ float2 unpack2(ull v) {
    float2 r;
    asm("mov.b64 {%0,%1}, %2;" : "=f"(r.x), "=f"(r.y) : "l"(v));
    return r;
}
// TF32 rounding (emulates the operand conversion JAX/cuBLAS TF32 matmuls apply)
__device__ __forceinline__ float tf32r(float x) {
    float r;
    asm("cvt.rna.tf32.f32 %0, %1;" : "=f"(r) : "f"(x));
    return r;
}
__device__ __forceinline__ float4 tf32r4(float4 v) {
    v.x = tf32r(v.x); v.y = tf32r(v.y); v.z = tf32r(v.z); v.w = tf32r(v.w);
    return v;
}

__global__ void __launch_bounds__(NTHREADS, 1)
rnn_scan_kernel(const float* __restrict__ u,
                const float* __restrict__ inoise,
                const float* __restrict__ rnoise,
                const float* __restrict__ Wrec,
                const float* __restrict__ brec,
                const float* __restrict__ Win,
                float* __restrict__ out)
{
    extern __shared__ char smem[];
    ulonglong2* Wq2  = (ulonglong2*)smem;                          // [K4][TILE_N] (tf32-rounded)
    ulonglong2* Hq2  = (ulonglong2*)(smem + SMEM_W_BYTES);         // [TILE_B][K4] swizzled (tf32-rounded)
    float4*     Wq4  = (float4*)Wq2;
    float4*     Hq4  = (float4*)Hq2;
    float*      v6   = (float*)(smem + SMEM_W_BYTES + SMEM_H_BYTES); // [16][8] (tf32-rounded)
    float*      WinS = v6 + TILE_B * 8;                            // [32][8] (tf32-rounded)
    float*      brecS= WinS + TILE_N * 8;                          // [32]
    ull*        shBase = (ull*)(brecS + TILE_N);                   // 8B aligned

    const int tid = threadIdx.x;
    const int bx  = blockIdx.x;
    const int bg  = bx >> 4;    // 0..7
    const int ng  = bx & 15;    // 0..15

    // ---------------- init: load W slice (resident forever, TF32-rounded), Win, brec ----------------
    const float4* WrecF4 = (const float4*)Wrec;
    for (int idx = tid; idx < TILE_N * K4; idx += NTHREADS) {
        int r = idx >> 7, k4 = idx & (K4 - 1);
        Wq4[k4 * TILE_N + r] = tf32r4(__ldg(&WrecF4[(ng * TILE_N + r) * K4 + k4]));
    }
    // TILE_N*NIN = 192 > NTHREADS — strided loop (the R3 guard bug left rows 22..31 unset).
    for (int idx = tid; idx < TILE_N * NIN; idx += NTHREADS) {
        int r = idx / NIN, i = idx - r * NIN;
        WinS[r * 8 + i] = tf32r(Win[(ng * TILE_N + r) * NIN + i]);
    }
    if (tid < TILE_N) brecS[tid] = brec[ng * TILE_N + tid];
    if (tid == 0) shBase[0] = *((volatile ull*)&g_flags[bx]);

    // zero out[:,0,:] tile and h_0 tile
    {
        float4 z = make_float4(0.f, 0.f, 0.f, 0.f);
        int r = tid >> 3, c = tid & 7;             // 16 rows x 8 float4
        int bG = bg * TILE_B + r;
        ((float4*)out)[(size_t)bG * (TSTEPS * NDIM / 4) + ng * 8 + c] = z;
        g_hbuf[0][bG * (NDIM / 4) + ng * 8 + c] = z;
    }
    __threadfence();
    __syncthreads();
    const ull base = shBase[0];
    if (tid == 0) *((volatile ull*)&g_flags[bx]) = base + 1ull;   // h_0 published

    // thread mapping: warp w owns n range [w*8, w*8+8); thread tile 2b x 2n
    const int w    = tid >> 5, lane = tid & 31;
    const int lb   = lane >> 2, ln = lane & 3;
    const int b0   = 2 * lb, b1 = b0 + 1;
    const int n0   = w * 8 + 2 * ln, n1 = n0 + 1;
    const int cs   = lb;                           // XOR swizzle constant = b>>1

    const int bG0 = bg * TILE_B + b0;
    const int bG1 = bG0 + 1;
    const int nG0 = ng * TILE_N + n0;

    for (int s = 1; s < TSTEPS; ++s) {
        // ---- prefetch step-local inputs (independent of h) before the barrier ----
        float2 rn0 = __ldg((const float2*)(rnoise + ((size_t)bG0 * TSTEPS + (s - 1)) * NDIM + nG0));
        float2 rn1 = __ldg((const float2*)(rnoise + ((size_t)bG1 * TSTEPS + (s - 1)) * NDIM + nG0));
        if (tid < TILE_B * NIN) {
            int r = tid / NIN, i = tid - r * NIN;
            int gi = ((bg * TILE_B + r) * TSTEPS + (s - 1)) * NIN + i;
            v6[r * 8 + i] = tf32r(__ldg(&u[gi]) + 0.6324555320336759f * __ldg(&inoise[gi]));
        }

        // ---- wait for all 16 CTAs of this batch group to publish h_{s-1} ----
        if (tid < NG_COUNT) {
            volatile ull* f = &g_flags[bg * NG_COUNT + tid];
            ull target = base + (ull)s;
            while (*f < target) {}
        }
        __syncthreads();
        __threadfence();

        // ---- unrounded h_{s-1} for the leak term (from L2, latency hidden) ----
        const float2* hfull = (const float2*)&g_hbuf[(s - 1) & 1][0];
        float2 ho0 = __ldcg(&hfull[((size_t)bG0 * NDIM + nG0) >> 1]);
        float2 ho1 = __ldcg(&hfull[((size_t)bG1 * NDIM + nG0) >> 1]);

        // ---- stage h tile [16 x 512] from L2 into swizzled SMEM, TF32-rounded ----
        const float4* hsrc = &g_hbuf[(s - 1) & 1][bg * TILE_B * (NDIM / 4)];
        for (int idx = tid; idx < TILE_B * K4; idx += NTHREADS) {
            int r = idx >> 7, k4 = idx & (K4 - 1);
            Hq4[r * K4 + (k4 ^ ((r >> 1) & 7))] = tf32r4(__ldcg(&hsrc[r * K4 + k4]));
        }
        __syncthreads();

        // ---- GEMM tile: 2b x 2n per thread, f32x2 packed FMA over k (TF32 operands) ----
        ull a00 = 0ull, a01 = 0ull, a10 = 0ull, a11 = 0ull;
        const ulonglong2* Hb0 = Hq2 + b0 * K4;
        const ulonglong2* Hb1 = Hq2 + b1 * K4;
        #pragma unroll 4
        for (int k4 = 0; k4 < K4; ++k4) {
            ulonglong2 h0 = Hb0[k4 ^ cs];
            ulonglong2 h1 = Hb1[k4 ^ cs];
            ulonglong2 w0 = Wq2[k4 * TILE_N + n0];
            ulonglong2 w1 = Wq2[k4 * TILE_N + n1];
            ffma2(a00, h0.x, w0.x); ffma2(a00, h0.y, w0.y);
            ffma2(a01, h0.x, w1.x); ffma2(a01, h0.y, w1.y);
            ffma2(a10, h1.x, w0.x); ffma2(a10, h1.y, w0.y);
            ffma2(a11, h1.x, w1.x); ffma2(a11, h1.y, w1.y);
        }
        float2 s00 = unpack2(a00), s01 = unpack2(a01);
        float2 s10 = unpack2(a10), s11 = unpack2(a11);
        float acc00 = s00.x + s00.y, acc01 = s01.x + s01.y;
        float acc10 = s10.x + s10.y, acc11 = s11.x + s11.y;

        // ---- input projection (IN=6, TF32 operands) ----
        float in00 = 0.f, in01 = 0.f, in10 = 0.f, in11 = 0.f;
        #pragma unroll
        for (int i = 0; i < NIN; ++i) {
            float vb0 = v6[b0 * 8 + i], vb1 = v6[b1 * 8 + i];
            float wn0 = WinS[n0 * 8 + i], wn1 = WinS[n1 * 8 + i];
            in00 += vb0 * wn0; in01 += vb0 * wn1;
            in10 += vb1 * wn0; in11 += vb1 * wn1;
        }
        float bn0 = brecS[n0], bn1 = brecS[n1];

        // ---- leak uses unrounded h_{s-1} ----
        float pre00 = (acc00 + bn0) + in00;
        float pre01 = (acc01 + bn1) + in01;
        float pre10 = (acc10 + bn0) + in10;
        float pre11 = (acc11 + bn1) + in11;
        float h00 = 0.8f * ho0.x + 0.2f * (fmaxf(pre00, 0.f) + rn0.x);
        float h01 = 0.8f * ho0.y + 0.2f * (fmaxf(pre01, 0.f) + rn0.y);
        float h10 = 0.8f * ho1.x + 0.2f * (fmaxf(pre10, 0.f) + rn1.x);
        float h11 = 0.8f * ho1.y + 0.2f * (fmaxf(pre11, 0.f) + rn1.y);

        // ---- publish h_s (ping-pong) and write output row t=s ----
        float2* hdst = (float2*)&g_hbuf[s & 1][0];
        hdst[((size_t)bG0 * NDIM + nG0) >> 1] = make_float2(h00, h01);
        hdst[((size_t)bG1 * NDIM + nG0) >> 1] = make_float2(h10, h11);
        float2* odst = (float2*)out;
        odst[(((size_t)bG0 * TSTEPS + s) * NDIM + nG0) >> 1] = make_float2(h00, h01);
        odst[(((size_t)bG1 * TSTEPS + s) * NDIM + nG0) >> 1] = make_float2(h10, h11);

        __threadfence();
        __syncthreads();
        if (tid == 0) *((volatile ull*)&g_flags[bx]) = base + (ull)s + 1ull;
    }
}

extern "C" void kernel_launch(void* const* d_in, const int* in_sizes, int n_in,
                              void* d_out, int out_size) {
    const float* u      = (const float*)d_in[0];
    const float* inoise = (const float*)d_in[1];
    const float* rnoise = (const float*)d_in[2];
    const float* Wrec   = (const float*)d_in[3];
    const float* brec   = (const float*)d_in[4];
    const float* Win    = (const float*)d_in[5];
    float* out = (float*)d_out;

    cudaFuncSetAttribute(rnn_scan_kernel,
                         cudaFuncAttributeMaxDynamicSharedMemorySize, SMEM_BYTES);
    rnn_scan_kernel<<<BG_COUNT * NG_COUNT, NTHREADS, SMEM_BYTES>>>(
        u, inoise, rnoise, Wrec, brec, Win, out);
}

// round 7
// speedup vs baseline: 1.8031x; 1.8031x over previous
#include <cuda_runtime.h>

typedef unsigned long long ull;

#define BATCH   128
#define TSTEPS  512
#define NDIM    512
#define NIN     6

#define BG_COUNT 8       // batch groups (16 rows each)
#define NG_COUNT 16      // n groups (32 cols each)
#define TILE_B   16
#define TILE_N   32
#define NTHREADS 256     // 8 warps: warps 0-3 k-half 0, warps 4-7 k-half 1
#define K4       128     // 512 / 4 (float4 chunks along k)
#define K4_HALF  64

#define FLAG_STRIDE 16   // ull per flag slot = 128B = one L2 line

#define SMEM_W_BYTES (K4 * TILE_N * 16)   // 65536
#define SMEM_H_BYTES (TILE_B * K4 * 16)   // 32768
// aux region: redsm (4KB) + v6 + WinS + brecS + shBase
#define AUX_BASE     (SMEM_W_BYTES + SMEM_H_BYTES)
#define RED_OFF      (AUX_BASE)                 // 4096 B (128 slots x 4 ull)
#define V6_OFF       (AUX_BASE + 4096)          // 512 B
#define WINS_OFF     (V6_OFF + 512)             // 1024 B
#define BREC_OFF     (WINS_OFF + 1024)          // 128 B
#define SHBASE_OFF   (BREC_OFF + 128)           // 8 B
#define SMEM_BYTES   (SHBASE_OFF + 64)

// Persistent scratch (allowed: __device__ globals). Ping-pong h buffers + padded flags.
__device__ float4 g_hbuf[2][BATCH * NDIM / 4];
__device__ ull    g_flags[BG_COUNT * NG_COUNT * FLAG_STRIDE];  // one 128B line per flag

__device__ __forceinline__ void ffma2(ull &acc, ull a, ull b) {
    asm("fma.rn.f32x2 %0, %1, %2, %0;" : "+l"(acc) : "l"(a), "l"(b));
}
__device__ __forceinline__ float2 unpack2(ull v) {
    float2 r;
    asm("mov.b64 {%0,%1}, %2;" : "=f"(r.x), "=f"(r.y) : "l"(v));
    return r;
}
// TF32 rounding (emulates the operand conversion JAX/cuBLAS TF32 matmuls apply)
__device__ __forceinline__ float tf32r(float x) {
    float r;
    asm("cvt.rna.tf32.f32 %0, %1;" : "=f"(r) : "f"(x));
    return r;
}
__device__ __forceinline__ float4 tf32r4(float4 v) {
    v.x = tf32r(v.x); v.y = tf32r(v.y); v.z = tf32r(v.z); v.w = tf32r(v.w);
    return v;
}
__device__ __forceinline__ ull ld_acquire_gpu(const ull* p) {
    ull v;
    asm volatile("ld.acquire.gpu.global.b64 %0, [%1];" : "=l"(v) : "l"(p) : "memory");
    return v;
}
__device__ __forceinline__ void st_release_gpu(ull* p, ull v) {
    asm volatile("st.release.gpu.global.b64 [%0], %1;" :: "l"(p), "l"(v) : "memory");
}

__global__ void __launch_bounds__(NTHREADS, 1)
rnn_scan_kernel(const float* __restrict__ u,
                const float* __restrict__ inoise,
                const float* __restrict__ rnoise,
                const float* __restrict__ Wrec,
                const float* __restrict__ brec,
                const float* __restrict__ Win,
                float* __restrict__ out)
{
    extern __shared__ char smem[];
    ulonglong2* Wq2  = (ulonglong2*)smem;                  // [K4][TILE_N] (tf32-rounded)
    ulonglong2* Hq2  = (ulonglong2*)(smem + SMEM_W_BYTES); // [TILE_B][K4] swizzled (tf32-rounded)
    float4*     Wq4  = (float4*)Wq2;
    float4*     Hq4  = (float4*)Hq2;
    ull*        redsm = (ull*)(smem + RED_OFF);            // [4][128]
    float*      v6   = (float*)(smem + V6_OFF);            // [16][8]
    float*      WinS = (float*)(smem + WINS_OFF);          // [32][8]
    float*      brecS= (float*)(smem + BREC_OFF);          // [32]
    ull*        shBase = (ull*)(smem + SHBASE_OFF);

    const int tid = threadIdx.x;
    const int bx  = blockIdx.x;
    const int bg  = bx >> 4;    // 0..7
    const int ng  = bx & 15;    // 0..15

    // ---------------- init: load W slice (resident forever, TF32-rounded), Win, brec ----------------
    const float4* WrecF4 = (const float4*)Wrec;
    for (int idx = tid; idx < TILE_N * K4; idx += NTHREADS) {
        int r = idx >> 7, k4 = idx & (K4 - 1);
        Wq4[k4 * TILE_N + r] = tf32r4(__ldg(&WrecF4[(ng * TILE_N + r) * K4 + k4]));
    }
    for (int idx = tid; idx < TILE_N * NIN; idx += NTHREADS) {
        int r = idx / NIN, i = idx - r * NIN;
        WinS[r * 8 + i] = tf32r(Win[(ng * TILE_N + r) * NIN + i]);
    }
    if (tid < TILE_N) brecS[tid] = brec[ng * TILE_N + tid];
    if (tid == 0) shBase[0] = *((volatile ull*)&g_flags[bx * FLAG_STRIDE]);

    // zero out[:,0,:] tile and h_0 tile
    if (tid < TILE_B * 8) {
        float4 z = make_float4(0.f, 0.f, 0.f, 0.f);
        int r = tid >> 3, c = tid & 7;             // 16 rows x 8 float4
        int bG = bg * TILE_B + r;
        ((float4*)out)[(size_t)bG * (TSTEPS * NDIM / 4) + ng * 8 + c] = z;
        g_hbuf[0][bG * (NDIM / 4) + ng * 8 + c] = z;
    }
    __syncthreads();
    const ull base = shBase[0];
    if (tid == 0) st_release_gpu(&g_flags[bx * FLAG_STRIDE], base + 1ull);  // h_0 published

    // thread mapping: within k-half, warp wk owns n range [wk*8, wk*8+8); thread tile 2b x 2n
    const int w    = tid >> 5, lane = tid & 31;
    const int wk   = w & 3;                        // n-mapping warp id
    const int kh   = w >> 2;                       // k-half: 0 => k4 [0,64), 1 => [64,128)
    const int kbase = kh * K4_HALF;
    const int lb   = lane >> 2, ln = lane & 3;
    const int b0   = 2 * lb, b1 = b0 + 1;
    const int n0   = wk * 8 + 2 * ln, n1 = n0 + 1;
    const int cs   = lb;                           // XOR swizzle constant

    const int bG0 = bg * TILE_B + b0;
    const int bG1 = bG0 + 1;
    const int nG0 = ng * TILE_N + n0;
    const int slot = wk * 32 + lane;               // reduction slot

    for (int s = 1; s < TSTEPS; ++s) {
        // ---- prefetch step-local inputs (independent of h) before the wait ----
        float2 rn0, rn1;
        if (kh == 0) {
            rn0 = __ldg((const float2*)(rnoise + ((size_t)bG0 * TSTEPS + (s - 1)) * NDIM + nG0));
            rn1 = __ldg((const float2*)(rnoise + ((size_t)bG1 * TSTEPS + (s - 1)) * NDIM + nG0));
        }
        if (tid < TILE_B * NIN) {
            int r = tid / NIN, i = tid - r * NIN;
            int gi = ((bg * TILE_B + r) * TSTEPS + (s - 1)) * NIN + i;
            v6[r * 8 + i] = tf32r(__ldg(&u[gi]) + 0.6324555320336759f * __ldg(&inoise[gi]));
        }

        // ---- wait for all 16 CTAs of this batch group to publish h_{s-1} ----
        if (tid < NG_COUNT) {
            const ull* f = &g_flags[(bg * NG_COUNT + tid) * FLAG_STRIDE];
            ull target = base + (ull)s;
            while (ld_acquire_gpu(f) < target) {}
        }
        __syncthreads();

        // ---- unrounded h_{s-1} for the leak term (from L2, latency hidden) ----
        float2 ho0, ho1;
        if (kh == 0) {
            const float2* hfull = (const float2*)&g_hbuf[(s - 1) & 1][0];
            ho0 = __ldcg(&hfull[((size_t)bG0 * NDIM + nG0) >> 1]);
            ho1 = __ldcg(&hfull[((size_t)bG1 * NDIM + nG0) >> 1]);
        }

        // ---- stage h tile [16 x 512] from L2 into swizzled SMEM, TF32-rounded ----
        const float4* hsrc = &g_hbuf[(s - 1) & 1][bg * TILE_B * (NDIM / 4)];
        for (int idx = tid; idx < TILE_B * K4; idx += NTHREADS) {
            int r = idx >> 7, k4 = idx & (K4 - 1);
            Hq4[r * K4 + (k4 ^ ((r >> 1) & 7))] = tf32r4(__ldcg(&hsrc[r * K4 + k4]));
        }
        __syncthreads();

        // ---- GEMM: each warp does its k-half, 2b x 2n per thread, f32x2 packed FMA ----
        ull a00 = 0ull, a01 = 0ull, a10 = 0ull, a11 = 0ull;
        const ulonglong2* Hb0 = Hq2 + b0 * K4;
        const ulonglong2* Hb1 = Hq2 + b1 * K4;
        #pragma unroll 4
        for (int kk = 0; kk < K4_HALF; ++kk) {
            int k4 = kbase + kk;
            ulonglong2 h0 = Hb0[k4 ^ cs];
            ulonglong2 h1 = Hb1[k4 ^ cs];
            ulonglong2 w0 = Wq2[k4 * TILE_N + n0];
            ulonglong2 w1 = Wq2[k4 * TILE_N + n1];
            ffma2(a00, h0.x, w0.x); ffma2(a00, h0.y, w0.y);
            ffma2(a01, h0.x, w1.x); ffma2(a01, h0.y, w1.y);
            ffma2(a10, h1.x, w0.x); ffma2(a10, h1.y, w0.y);
            ffma2(a11, h1.x, w1.x); ffma2(a11, h1.y, w1.y);
        }

        // ---- k-half 1 warps publish partials to smem; k-half 0 warps reduce + epilogue ----
        if (kh == 1) {
            redsm[0 * 128 + slot] = a00;
            redsm[1 * 128 + slot] = a01;
            redsm[2 * 128 + slot] = a10;
            redsm[3 * 128 + slot] = a11;
        }
        __syncthreads();

        if (kh == 0) {
            ull r00 = redsm[0 * 128 + slot];
            ull r01 = redsm[1 * 128 + slot];
            ull r10 = redsm[2 * 128 + slot];
            ull r11 = redsm[3 * 128 + slot];
            float2 s00 = unpack2(a00), p00 = unpack2(r00);
            float2 s01 = unpack2(a01), p01 = unpack2(r01);
            float2 s10 = unpack2(a10), p10 = unpack2(r10);
            float2 s11 = unpack2(a11), p11 = unpack2(r11);
            float acc00 = (s00.x + s00.y) + (p00.x + p00.y);
            float acc01 = (s01.x + s01.y) + (p01.x + p01.y);
            float acc10 = (s10.x + s10.y) + (p10.x + p10.y);
            float acc11 = (s11.x + s11.y) + (p11.x + p11.y);

            // input projection (IN=6, TF32 operands)
            float in00 = 0.f, in01 = 0.f, in10 = 0.f, in11 = 0.f;
            #pragma unroll
            for (int i = 0; i < NIN; ++i) {
                float vb0 = v6[b0 * 8 + i], vb1 = v6[b1 * 8 + i];
                float wn0 = WinS[n0 * 8 + i], wn1 = WinS[n1 * 8 + i];
                in00 += vb0 * wn0; in01 += vb0 * wn1;
                in10 += vb1 * wn0; in11 += vb1 * wn1;
            }
            float bn0 = brecS[n0], bn1 = brecS[n1];

            float pre00 = (acc00 + bn0) + in00;
            float pre01 = (acc01 + bn1) + in01;
            float pre10 = (acc10 + bn0) + in10;
            float pre11 = (acc11 + bn1) + in11;
            float h00 = 0.8f * ho0.x + 0.2f * (fmaxf(pre00, 0.f) + rn0.x);
            float h01 = 0.8f * ho0.y + 0.2f * (fmaxf(pre01, 0.f) + rn0.y);
            float h10 = 0.8f * ho1.x + 0.2f * (fmaxf(pre10, 0.f) + rn1.x);
            float h11 = 0.8f * ho1.y + 0.2f * (fmaxf(pre11, 0.f) + rn1.y);

            // publish h_s (ping-pong)
            float2* hdst = (float2*)&g_hbuf[s & 1][0];
            hdst[((size_t)bG0 * NDIM + nG0) >> 1] = make_float2(h00, h01);
            hdst[((size_t)bG1 * NDIM + nG0) >> 1] = make_float2(h10, h11);

            __syncthreads();                               // all h stores done CTA-wide
            if (tid == 0)
                st_release_gpu(&g_flags[bx * FLAG_STRIDE], base + (ull)s + 1ull);

            // out write AFTER the release — off the inter-CTA critical path
            float2* odst = (float2*)out;
            odst[(((size_t)bG0 * TSTEPS + s) * NDIM + nG0) >> 1] = make_float2(h00, h01);
            odst[(((size_t)bG1 * TSTEPS + s) * NDIM + nG0) >> 1] = make_float2(h10, h11);
        } else {
            __syncthreads();                               // matching barrier
        }
    }
}

extern "C" void kernel_launch(void* const* d_in, const int* in_sizes, int n_in,
                              void* d_out, int out_size) {
    const float* u      = (const float*)d_in[0];
    const float* inoise = (const float*)d_in[1];
    const float* rnoise = (const float*)d_in[2];
    const float* Wrec   = (const float*)d_in[3];
    const float* brec   = (const float*)d_in[4];
    const float* Win    = (const float*)d_in[5];
    float* out = (float*)d_out;

    cudaFuncSetAttribute(rnn_scan_kernel,
                         cudaFuncAttributeMaxDynamicSharedMemorySize, SMEM_BYTES);
    rnn_scan_kernel<<<BG_COUNT * NG_COUNT, NTHREADS, SMEM_BYTES>>>(
        u, inoise, rnoise, Wrec, brec, Win, out);
}

// round 10
// speedup vs baseline: 1.8106x; 1.0041x over previous
#include <cuda_runtime.h>

typedef unsigned long long ull;

#define BATCH   128
#define TSTEPS  512
#define NDIM    512
#define NIN     6

#define BG_COUNT 8       // batch groups (16 rows each)
#define NG_COUNT 16      // n groups (32 cols each)
#define TILE_B   16
#define TILE_N   32
#define NTHREADS 256     // 8 warps: warps 0-3 k-half 0, warps 4-7 k-half 1
#define K4       128     // 512 / 4 (float4 chunks along k)
#define K4_HALF  64

#define FLAG_STRIDE 16   // ull per flag slot = 128B = one L2 line

#define SMEM_W_BYTES (K4 * TILE_N * 16)   // 65536
#define SMEM_H_BYTES (TILE_B * K4 * 16)   // 32768
#define AUX_BASE     (SMEM_W_BYTES + SMEM_H_BYTES)
#define RED_OFF      (AUX_BASE)                 // 4096 B (128 slots x 4 ull)
#define V6_OFF       (AUX_BASE + 4096)          // 512 B
#define WINS_OFF     (V6_OFF + 512)             // 1024 B
#define BREC_OFF     (WINS_OFF + 1024)          // 128 B
#define SHBASE_OFF   (BREC_OFF + 128)           // 8 B
#define MBAR_OFF     (SHBASE_OFF + 8)           // 8 B (8-aligned)
#define SMEM_BYTES   (MBAR_OFF + 24)

// Persistent scratch. g_hbuf holds TF32-ROUNDED h in the consumer's swizzled
// SMEM image layout: within batch-group bg, float4 index = r*K4 + (k4 ^ ((r>>1)&7)).
__device__ float4 g_hbuf[2][BATCH * NDIM / 4];
__device__ ull    g_flags[BG_COUNT * NG_COUNT * FLAG_STRIDE];  // one 128B line per flag

__device__ __forceinline__ void ffma2(ull &acc, ull a, ull b) {
    asm("fma.rn.f32x2 %0, %1, %2, %0;" : "+l"(acc) : "l"(a), "l"(b));
}
__device__ __forceinline__ float2 unpack2(ull v) {
    float2 r;
    asm("mov.b64 {%0,%1}, %2;" : "=f"(r.x), "=f"(r.y) : "l"(v));
    return r;
}
__device__ __forceinline__ float tf32r(float x) {
    float r;
    asm("cvt.rna.tf32.f32 %0, %1;" : "=f"(r) : "f"(x));
    return r;
}
__device__ __forceinline__ float4 tf32r4(float4 v) {
    v.x = tf32r(v.x); v.y = tf32r(v.y); v.z = tf32r(v.z); v.w = tf32r(v.w);
    return v;
}
__device__ __forceinline__ ull ld_acquire_gpu(const ull* p) {
    ull v;
    asm volatile("ld.acquire.gpu.global.b64 %0, [%1];" : "=l"(v) : "l"(p) : "memory");
    return v;
}
__device__ __forceinline__ void st_release_gpu(ull* p, ull v) {
    asm volatile("st.release.gpu.global.b64 [%0], %1;" :: "l"(p), "l"(v) : "memory");
}
__device__ __forceinline__ void mbar_wait_parity(unsigned mbar, unsigned parity) {
    unsigned done;
    asm volatile(
        "{\n\t.reg .pred p;\n\t"
        "mbarrier.try_wait.parity.acquire.cta.shared::cta.b64 p, [%1], %2;\n\t"
        "selp.b32 %0, 1, 0, p;\n\t}"
        : "=r"(done) : "r"(mbar), "r"(parity) : "memory");
    if (!done) {
        asm volatile(
            "{\n\t.reg .pred P1;\n\t"
            "WL_%=:\n\t"
            "mbarrier.try_wait.parity.acquire.cta.shared::cta.b64 P1, [%0], %1, 0x989680;\n\t"
            "@P1 bra.uni WD_%=;\n\t"
            "bra.uni WL_%=;\n\t"
            "WD_%=:\n\t}"
            :: "r"(mbar), "r"(parity) : "memory");
    }
}

__global__ void __launch_bounds__(NTHREADS, 1)
rnn_scan_kernel(const float* __restrict__ u,
                const float* __restrict__ inoise,
                const float* __restrict__ rnoise,
                const float* __restrict__ Wrec,
                const float* __restrict__ brec,
                const float* __restrict__ Win,
                float* __restrict__ out)
{
    extern __shared__ char smem[];
    ulonglong2* Wq2  = (ulonglong2*)smem;                  // [K4][TILE_N] (tf32-rounded)
    ulonglong2* Hq2  = (ulonglong2*)(smem + SMEM_W_BYTES); // [TILE_B][K4] swizzled (tf32)
    float4*     Wq4  = (float4*)Wq2;
    ull*        redsm = (ull*)(smem + RED_OFF);            // [4][128]
    float*      v6   = (float*)(smem + V6_OFF);            // [16][8]
    float*      WinS = (float*)(smem + WINS_OFF);          // [32][8]
    float*      brecS= (float*)(smem + BREC_OFF);          // [32]
    ull*        shBase = (ull*)(smem + SHBASE_OFF);

    const int tid = threadIdx.x;
    const int bx  = blockIdx.x;
    const int bg  = bx >> 4;    // 0..7
    const int ng  = bx & 15;    // 0..15

    const unsigned hq_addr   = (unsigned)__cvta_generic_to_shared(smem + SMEM_W_BYTES);
    const unsigned mbar_addr = (unsigned)__cvta_generic_to_shared(smem + MBAR_OFF);

    // ---------------- init: W slice (resident, TF32-rounded), Win, brec, mbarrier ----------------
    const float4* WrecF4 = (const float4*)Wrec;
    for (int idx = tid; idx < TILE_N * K4; idx += NTHREADS) {
        int r = idx >> 7, k4 = idx & (K4 - 1);
        Wq4[k4 * TILE_N + r] = tf32r4(__ldg(&WrecF4[(ng * TILE_N + r) * K4 + k4]));
    }
    for (int idx = tid; idx < TILE_N * NIN; idx += NTHREADS) {
        int r = idx / NIN, i = idx - r * NIN;
        WinS[r * 8 + i] = tf32r(Win[(ng * TILE_N + r) * NIN + i]);
    }
    if (tid < TILE_N) brecS[tid] = brec[ng * TILE_N + tid];
    if (tid == 0) {
        shBase[0] = *((volatile ull*)&g_flags[bx * FLAG_STRIDE]);
        asm volatile("mbarrier.init.shared.b64 [%0], %1;" :: "r"(mbar_addr), "r"(1u) : "memory");
    }

    // zero out[:,0,:] tile and h_0 tile (zeros are TF32-exact; swizzle irrelevant)
    if (tid < TILE_B * 8) {
        float4 z = make_float4(0.f, 0.f, 0.f, 0.f);
        int r = tid >> 3, c = tid & 7;
        int bG = bg * TILE_B + r;
        ((float4*)out)[(size_t)bG * (TSTEPS * NDIM / 4) + ng * 8 + c] = z;
        g_hbuf[0][bG * (NDIM / 4) + ng * 8 + c] = z;
    }
    __syncthreads();
    const ull base = shBase[0];
    if (tid == 0) st_release_gpu(&g_flags[bx * FLAG_STRIDE], base + 1ull);  // h_0 published

    // thread mapping: within k-half, warp wk owns n range [wk*8, wk*8+8); thread tile 2b x 2n
    const int w    = tid >> 5, lane = tid & 31;
    const int wk   = w & 3;
    const int kh   = w >> 2;                       // k-half
    const int kbase = kh * K4_HALF;
    const int lb   = lane >> 2, ln = lane & 3;
    const int b0   = 2 * lb, b1 = b0 + 1;
    const int n0   = wk * 8 + 2 * ln, n1 = n0 + 1;
    const int cs   = lb;                           // XOR swizzle constant = (b>>1)&7

    const int bG0 = bg * TILE_B + b0;
    const int bG1 = bG0 + 1;
    const int nG0 = ng * TILE_N + n0;
    const int slot = wk * 32 + lane;

    // publish addresses (bytes) in swizzled g_hbuf layout
    const int k4p   = nG0 >> 2;
    const int subo  = (nG0 & 3) * 4;               // 0 or 8 bytes within float4
    const size_t pub0 = ((size_t)(bg * TILE_B + b0) * K4 + (k4p ^ lb)) * 16 + subo;
    const size_t pub1 = ((size_t)(bg * TILE_B + b1) * K4 + (k4p ^ lb)) * 16 + subo;
    const ull g_src_base = (ull)__cvta_generic_to_global(&g_hbuf[0][bg * TILE_B * (NDIM / 4)]);
    const ull g_buf_stride = (ull)((char*)&g_hbuf[1][0] - (char*)&g_hbuf[0][0]);

    // exact h_{s-1} for the leak term lives in registers (this thread produced it)
    float hp00 = 0.f, hp01 = 0.f, hp10 = 0.f, hp11 = 0.f;

    for (int s = 1; s < TSTEPS; ++s) {
        // ---- prefetch step-local inputs (independent of h) before the wait ----
        float2 rn0, rn1;
        if (kh == 0) {
            rn0 = __ldg((const float2*)(rnoise + ((size_t)bG0 * TSTEPS + (s - 1)) * NDIM + nG0));
            rn1 = __ldg((const float2*)(rnoise + ((size_t)bG1 * TSTEPS + (s - 1)) * NDIM + nG0));
        }
        if (tid < TILE_B * NIN) {
            int r = tid / NIN, i = tid - r * NIN;
            int gi = ((bg * TILE_B + r) * TSTEPS + (s - 1)) * NIN + i;
            v6[r * 8 + i] = tf32r(__ldg(&u[gi]) + 0.6324555320336759f * __ldg(&inoise[gi]));
        }

        // ---- wait for all 16 CTAs of this batch group to publish h_{s-1} ----
        if (tid < NG_COUNT) {
            const ull* f = &g_flags[(bg * NG_COUNT + tid) * FLAG_STRIDE];
            ull target = base + (ull)s;
            while (ld_acquire_gpu(f) < target) {}
        }
        __syncthreads();

        // ---- bulk-copy h tile [16 x 512] (pre-rounded, pre-swizzled) L2 -> SMEM ----
        if (tid == 0) {
            ull gsrc = g_src_base + (ull)((s - 1) & 1) * g_buf_stride;
            asm volatile("fence.proxy.async;" ::: "memory");
            asm volatile("mbarrier.arrive.expect_tx.shared.b64 _, [%0], %1;"
                         :: "r"(mbar_addr), "r"((unsigned)SMEM_H_BYTES) : "memory");
            asm volatile("cp.async.bulk.shared::cluster.global.mbarrier::complete_tx::bytes [%0], [%1], %2, [%3];"
                         :: "r"(hq_addr), "l"(gsrc), "r"((unsigned)SMEM_H_BYTES), "r"(mbar_addr)
                         : "memory");
        }
        mbar_wait_parity(mbar_addr, (unsigned)((s - 1) & 1));

        // ---- GEMM: each warp does its k-half, 2b x 2n per thread, f32x2 packed FMA ----
        ull a00 = 0ull, a01 = 0ull, a10 = 0ull, a11 = 0ull;
        const ulonglong2* Hb0 = Hq2 + b0 * K4;
        const ulonglong2* Hb1 = Hq2 + b1 * K4;
        #pragma unroll 4
        for (int kk = 0; kk < K4_HALF; ++kk) {
            int k4 = kbase + kk;
            ulonglong2 h0 = Hb0[k4 ^ cs];
            ulonglong2 h1 = Hb1[k4 ^ cs];
            ulonglong2 w0 = Wq2[k4 * TILE_N + n0];
            ulonglong2 w1 = Wq2[k4 * TILE_N + n1];
            ffma2(a00, h0.x, w0.x); ffma2(a00, h0.y, w0.y);
            ffma2(a01, h0.x, w1.x); ffma2(a01, h0.y, w1.y);
            ffma2(a10, h1.x, w0.x); ffma2(a10, h1.y, w0.y);
            ffma2(a11, h1.x, w1.x); ffma2(a11, h1.y, w1.y);
        }

        // ---- k-half 1 warps publish partials; k-half 0 warps reduce + epilogue ----
        if (kh == 1) {
            redsm[0 * 128 + slot] = a00;
            redsm[1 * 128 + slot] = a01;
            redsm[2 * 128 + slot] = a10;
            redsm[3 * 128 + slot] = a11;
        }
        __syncthreads();

        if (kh == 0) {
            float2 s00 = unpack2(a00), p00 = unpack2(redsm[0 * 128 + slot]);
            float2 s01 = unpack2(a01), p01 = unpack2(redsm[1 * 128 + slot]);
            float2 s10 = unpack2(a10), p10 = unpack2(redsm[2 * 128 + slot]);
            float2 s11 = unpack2(a11), p11 = unpack2(redsm[3 * 128 + slot]);
            float acc00 = (s00.x + s00.y) + (p00.x + p00.y);
            float acc01 = (s01.x + s01.y) + (p01.x + p01.y);
            float acc10 = (s10.x + s10.y) + (p10.x + p10.y);
            float acc11 = (s11.x + s11.y) + (p11.x + p11.y);

            float in00 = 0.f, in01 = 0.f, in10 = 0.f, in11 = 0.f;
            #pragma unroll
            for (int i = 0; i < NIN; ++i) {
                float vb0 = v6[b0 * 8 + i], vb1 = v6[b1 * 8 + i];
                float wn0 = WinS[n0 * 8 + i], wn1 = WinS[n1 * 8 + i];
                in00 += vb0 * wn0; in01 += vb0 * wn1;
                in10 += vb1 * wn0; in11 += vb1 * wn1;
            }
            float bn0 = brecS[n0], bn1 = brecS[n1];

            float pre00 = (acc00 + bn0) + in00;
            float pre01 = (acc01 + bn1) + in01;
            float pre10 = (acc10 + bn0) + in10;
            float pre11 = (acc11 + bn1) + in11;
            float h00 = 0.8f * hp00 + 0.2f * (fmaxf(pre00, 0.f) + rn0.x);
            float h01 = 0.8f * hp01 + 0.2f * (fmaxf(pre01, 0.f) + rn0.y);
            float h10 = 0.8f * hp10 + 0.2f * (fmaxf(pre10, 0.f) + rn1.x);
            float h11 = 0.8f * hp11 + 0.2f * (fmaxf(pre11, 0.f) + rn1.y);
            hp00 = h00; hp01 = h01; hp10 = h10; hp11 = h11;

            // publish TF32-rounded h_s into the swizzled image (ping-pong)
            char* hb = (char*)&g_hbuf[s & 1][0];
            *(float2*)(hb + pub0) = make_float2(tf32r(h00), tf32r(h01));
            *(float2*)(hb + pub1) = make_float2(tf32r(h10), tf32r(h11));

            __syncthreads();                               // all h stores done CTA-wide
            if (tid == 0)
                st_release_gpu(&g_flags[bx * FLAG_STRIDE], base + (ull)s + 1ull);

            // out write AFTER the release — off the inter-CTA critical path
            float2* odst = (float2*)out;
            odst[(((size_t)bG0 * TSTEPS + s) * NDIM + nG0) >> 1] = make_float2(h00, h01);
            odst[(((size_t)bG1 * TSTEPS + s) * NDIM + nG0) >> 1] = make_float2(h10, h11);
        } else {
            __syncthreads();                               // matching barrier
        }
    }
}

extern "C" void kernel_launch(void* const* d_in, const int* in_sizes, int n_in,
                              void* d_out, int out_size) {
    const float* u      = (const float*)d_in[0];
    const float* inoise = (const float*)d_in[1];
    const float* rnoise = (const float*)d_in[2];
    const float* Wrec   = (const float*)d_in[3];
    const float* brec   = (const float*)d_in[4];
    const float* Win    = (const float*)d_in[5];
    float* out = (float*)d_out;

    cudaFuncSetAttribute(rnn_scan_kernel,
                         cudaFuncAttributeMaxDynamicSharedMemorySize, SMEM_BYTES);
    rnn_scan_kernel<<<BG_COUNT * NG_COUNT, NTHREADS, SMEM_BYTES>>>(
        u, inoise, rnoise, Wrec, brec, Win, out);
}